// round 4
// baseline (speedup 1.0000x reference)
#include <cuda_runtime.h>
#include <cuda_bf16.h>
#include <cstdint>

// ===========================================================================
// MoE AG-scatter grouped GEMM via mma.sync bf16, 2-term fp32 split (3 products)
//   out[s,:] = x[token(s),:] @ W[e(s),:,:]^T
// R4: CTA tile 128x256 (warp tile 64x64, 2Mx4N warps), persistent job loop,
//     A split stored per-token (8192 rows) and gathered in-GEMM via smem token
//     list. Double-buffered cp.async, 80B-stride padded smem, ldmatrix.
// ===========================================================================

#define NTOK   8192
#define TOPK   2
#define MTOT   (NTOK * TOPK)          // 16384
#define NDIM   1024
#define KDIM   1024
#define NEXP   8

#define BM     128
#define BN     256
#define BK     32                     // bf16 k per chunk
#define NCHUNK (KDIM / BK)            // 32
#define NBLK   (NDIM / BN)            // 4
#define MAXTILES (MTOT / BM + NEXP)   // 136

#define ASTR   80                     // smem row stride (64B data + 16B pad)
// stage rows: AH 0-127, AL 128-255, BH 256-511, BL 512-767
#define OFF_AH 0
#define OFF_AL (128 * ASTR)
#define OFF_BH (256 * ASTR)
#define OFF_BL (512 * ASTR)
#define STAGE_BYTES (768 * ASTR)      // 61440
#define SMEM_TOTAL  (2 * STAGE_BYTES + 512 + 16)   // + token list + job slot

// ---------------- device-global scratch ------------------------------------
__device__ int g_token_of_row[MTOT];
__device__ int g_tile_e[MAXTILES];
__device__ int g_tile_row0[MAXTILES];
__device__ int g_tile_rows[MAXTILES];
__device__ int g_njobs;
__device__ int g_job;
__device__ __align__(16) __nv_bfloat16 g_A_hi[(size_t)NTOK * KDIM];
__device__ __align__(16) __nv_bfloat16 g_A_lo[(size_t)NTOK * KDIM];
__device__ __align__(16) __nv_bfloat16 g_W_hi[(size_t)NEXP * NDIM * KDIM];
__device__ __align__(16) __nv_bfloat16 g_W_lo[(size_t)NEXP * NDIM * KDIM];

// ---------------- helpers ---------------------------------------------------
__device__ __forceinline__ uint32_t smem_to_u32(const void* p) {
    uint32_t a;
    asm("{ .reg .u64 t; cvta.to.shared.u64 t, %1; cvt.u32.u64 %0, t; }"
        : "=r"(a) : "l"(p));
    return a;
}

#define CPA16(dst_u32, src_ptr) \
    asm volatile("cp.async.cg.shared.global [%0], [%1], 16;" \
        :: "r"(dst_u32), "l"(src_ptr))
#define CPA_COMMIT() asm volatile("cp.async.commit_group;")
#define CPA_WAIT1()  asm volatile("cp.async.wait_group 1;")
#define CPA_WAIT0()  asm volatile("cp.async.wait_group 0;")

__device__ __forceinline__ void ldsm_x4(uint32_t r[4], uint32_t addr) {
    asm volatile("ldmatrix.sync.aligned.m8n8.x4.shared.b16 {%0,%1,%2,%3}, [%4];"
        : "=r"(r[0]), "=r"(r[1]), "=r"(r[2]), "=r"(r[3]) : "r"(addr));
}

__device__ __forceinline__ void mma_bf16(float d[4],
    const uint32_t a[4], uint32_t b0, uint32_t b1)
{
    asm volatile(
        "mma.sync.aligned.m16n8k16.row.col.f32.bf16.bf16.f32 "
        "{%0,%1,%2,%3}, {%4,%5,%6,%7}, {%8,%9}, {%0,%1,%2,%3};"
        : "+f"(d[0]), "+f"(d[1]), "+f"(d[2]), "+f"(d[3])
        : "r"(a[0]), "r"(a[1]), "r"(a[2]), "r"(a[3]), "r"(b0), "r"(b1));
}

// ---------------- prep kernels ----------------------------------------------
__global__ void build_token_map(const int* __restrict__ scatter) {
    int f = blockIdx.x * blockDim.x + threadIdx.x;
    if (f < MTOT) g_token_of_row[scatter[f]] = f / TOPK;
}

__global__ void build_tiles(const int* __restrict__ splits) {
    if (threadIdx.x != 0) return;
    int cum = 0, t = 0;
    for (int e = 0; e < NEXP; e++) {
        int cnt = splits[e];
        for (int r0 = 0; r0 < cnt; r0 += BM) {
            g_tile_e[t] = e;
            g_tile_row0[t] = cum + r0;
            g_tile_rows[t] = (cnt - r0 < BM) ? (cnt - r0) : BM;
            t++;
        }
        cum += cnt;
    }
    g_njobs = t * NBLK;
    g_job = 0;
}

// split x (per token, no gather) -> bf16 hi/lo
__global__ __launch_bounds__(256) void split_A(const float* __restrict__ x) {
    int idx = blockIdx.x * 256 + threadIdx.x;       // NTOK*KDIM/4 threads
    size_t o = (size_t)idx * 4;
    float4 v = *(const float4*)(x + o);
    __nv_bfloat16 h0 = __float2bfloat16(v.x), h1 = __float2bfloat16(v.y);
    __nv_bfloat16 h2 = __float2bfloat16(v.z), h3 = __float2bfloat16(v.w);
    __nv_bfloat16 l0 = __float2bfloat16(v.x - __bfloat162float(h0));
    __nv_bfloat16 l1 = __float2bfloat16(v.y - __bfloat162float(h1));
    __nv_bfloat16 l2 = __float2bfloat16(v.z - __bfloat162float(h2));
    __nv_bfloat16 l3 = __float2bfloat16(v.w - __bfloat162float(h3));
    *(ushort4*)(g_A_hi + o) = make_ushort4(
        __bfloat16_as_ushort(h0), __bfloat16_as_ushort(h1),
        __bfloat16_as_ushort(h2), __bfloat16_as_ushort(h3));
    *(ushort4*)(g_A_lo + o) = make_ushort4(
        __bfloat16_as_ushort(l0), __bfloat16_as_ushort(l1),
        __bfloat16_as_ushort(l2), __bfloat16_as_ushort(l3));
}

__global__ __launch_bounds__(256) void split_W(const float* __restrict__ w) {
    int idx = blockIdx.x * 256 + threadIdx.x;       // NEXP*NDIM*KDIM/4 threads
    size_t o = (size_t)idx * 4;
    float4 v = *(const float4*)(w + o);
    __nv_bfloat16 h0 = __float2bfloat16(v.x), h1 = __float2bfloat16(v.y);
    __nv_bfloat16 h2 = __float2bfloat16(v.z), h3 = __float2bfloat16(v.w);
    __nv_bfloat16 l0 = __float2bfloat16(v.x - __bfloat162float(h0));
    __nv_bfloat16 l1 = __float2bfloat16(v.y - __bfloat162float(h1));
    __nv_bfloat16 l2 = __float2bfloat16(v.z - __bfloat162float(h2));
    __nv_bfloat16 l3 = __float2bfloat16(v.w - __bfloat162float(h3));
    *(ushort4*)(g_W_hi + o) = make_ushort4(
        __bfloat16_as_ushort(h0), __bfloat16_as_ushort(h1),
        __bfloat16_as_ushort(h2), __bfloat16_as_ushort(h3));
    *(ushort4*)(g_W_lo + o) = make_ushort4(
        __bfloat16_as_ushort(l0), __bfloat16_as_ushort(l1),
        __bfloat16_as_ushort(l2), __bfloat16_as_ushort(l3));
}

// ---------------- main GEMM --------------------------------------------------
// One stage = 768 rows x 64B data (80B stride): 3072 x 16B cp.async, 12/thread.
__device__ __forceinline__ void load_stage(uint32_t sbuf, int c, int wbase,
                                           const int* s_tok, int tid)
{
    const size_t kb = (size_t)c * BK;
    #pragma unroll
    for (int i = 0; i < 12; i++) {
        int o   = tid + i * 256;          // 0..3071
        int row = o >> 2;                 // 0..767
        int seg = (o & 3) * 16;
        uint32_t dst = sbuf + row * ASTR + seg;
        const char* src;
        if (row < 256) {                  // A hi/lo, gathered by token
            int r   = row & 127;
            int tok = s_tok[r];
            const __nv_bfloat16* base = (row < 128) ? g_A_hi : g_A_lo;
            src = (const char*)(base + (size_t)tok * KDIM + kb) + seg;
        } else {                          // B hi/lo
            int br = row - 256;
            int r  = br & 255;
            const __nv_bfloat16* base = (br < 256) ? g_W_hi : g_W_lo;
            src = (const char*)(base + (size_t)(wbase + r) * KDIM + kb) + seg;
        }
        CPA16(dst, src);
    }
}

__global__ __launch_bounds__(256, 1) void moe_gemm_mma(float* __restrict__ out)
{
    extern __shared__ char smem_raw[];
    const uint32_t st0 = smem_to_u32(smem_raw);
    const uint32_t st1 = st0 + STAGE_BYTES;
    int* s_tok = (int*)(smem_raw + 2 * STAGE_BYTES);
    int* s_job = (int*)(smem_raw + 2 * STAGE_BYTES + 512);

    const int tid  = threadIdx.x;
    const int wid  = tid >> 5;
    const int lane = tid & 31;
    const int wm   = wid & 1;          // 2 warps along M (64 rows each)
    const int wn   = wid >> 1;         // 4 warps along N (64 cols each)

    // ldmatrix per-lane offsets (within a stage)
    const int a_r   = (lane & 7) + ((lane >> 3) & 1) * 8;
    const int a_c16 = lane >> 4;
    uint32_t offA[4];
    #pragma unroll
    for (int mt = 0; mt < 4; mt++)
        offA[mt] = (wm * 64 + mt * 16 + a_r) * ASTR + a_c16 * 16;
    const int b_r   = (lane & 7) + ((lane >> 4) & 1) * 8;
    const int b_k16 = (lane >> 3) & 1;
    uint32_t offB[4];
    #pragma unroll
    for (int np = 0; np < 4; np++)
        offB[np] = (wn * 64 + np * 16 + b_r) * ASTR + b_k16 * 16;

    const int njobs = g_njobs;

    while (true) {
        __syncthreads();                           // stages + s_tok free
        if (tid == 0) *s_job = atomicAdd(&g_job, 1);
        __syncthreads();
        const int job = *s_job;
        if (job >= njobs) break;

        const int tile = job >> 2;                 // NBLK = 4
        const int nb   = job & 3;
        const int nrows = g_tile_rows[tile];
        const int row0  = g_tile_row0[tile];
        const int e     = g_tile_e[tile];
        const int n0    = nb * BN;
        const int wbase = e * NDIM + n0;

        if (tid < 128)
            s_tok[tid] = (tid < nrows) ? g_token_of_row[row0 + tid] : 0;
        __syncthreads();

        float acc[4][8][4];
        #pragma unroll
        for (int mt = 0; mt < 4; mt++)
            #pragma unroll
            for (int nt = 0; nt < 8; nt++)
                #pragma unroll
                for (int q = 0; q < 4; q++)
                    acc[mt][nt][q] = 0.0f;

        load_stage(st0, 0, wbase, s_tok, tid);
        CPA_COMMIT();
        load_stage(st1, 1, wbase, s_tok, tid);
        CPA_COMMIT();

        for (int c = 0; c < NCHUNK; c++) {
            const uint32_t sbuf = (c & 1) ? st1 : st0;
            if (c < NCHUNK - 1) { CPA_WAIT1(); } else { CPA_WAIT0(); }
            __syncthreads();

            #pragma unroll
            for (int ks = 0; ks < 2; ks++) {
                const uint32_t ko = ks * 32;       // 16 bf16 = 32B
                uint32_t Bh[4][4], Bl[4][4];
                #pragma unroll
                for (int np = 0; np < 4; np++) {
                    ldsm_x4(Bh[np], sbuf + OFF_BH + offB[np] + ko);
                    ldsm_x4(Bl[np], sbuf + OFF_BL + offB[np] + ko);
                }
                #pragma unroll
                for (int mt = 0; mt < 4; mt++) {
                    uint32_t Ah[4], Al[4];
                    ldsm_x4(Ah, sbuf + OFF_AH + offA[mt] + ko);
                    ldsm_x4(Al, sbuf + OFF_AL + offA[mt] + ko);
                    #pragma unroll
                    for (int np = 0; np < 4; np++) {
                        float* d0 = acc[mt][2 * np];
                        float* d1 = acc[mt][2 * np + 1];
                        mma_bf16(d0, Ah, Bh[np][0], Bh[np][1]);
                        mma_bf16(d1, Ah, Bh[np][2], Bh[np][3]);
                        mma_bf16(d0, Ah, Bl[np][0], Bl[np][1]);
                        mma_bf16(d1, Ah, Bl[np][2], Bl[np][3]);
                        mma_bf16(d0, Al, Bh[np][0], Bh[np][1]);
                        mma_bf16(d1, Al, Bh[np][2], Bh[np][3]);
                    }
                }
            }

            __syncthreads();
            if (c + 2 < NCHUNK) {
                load_stage(sbuf, c + 2, wbase, s_tok, tid);
                CPA_COMMIT();
            }
        }

        // epilogue: lane holds rows g, g+8 and cols 2t, 2t+1 of each mma tile
        const int g = lane >> 2;
        const int t = lane & 3;
        #pragma unroll
        for (int mt = 0; mt < 4; mt++) {
            const int mBase = wm * 64 + mt * 16;
            const int m0 = mBase + g;
            const int m1 = mBase + g + 8;
            float* r0p = out + (size_t)(row0 + m0) * NDIM + n0 + wn * 64 + 2 * t;
            float* r1p = out + (size_t)(row0 + m1) * NDIM + n0 + wn * 64 + 2 * t;
            #pragma unroll
            for (int nt = 0; nt < 8; nt++) {
                if (m0 < nrows) {
                    float2 v; v.x = acc[mt][nt][0]; v.y = acc[mt][nt][1];
                    *(float2*)(r0p + nt * 8) = v;
                }
                if (m1 < nrows) {
                    float2 v; v.x = acc[mt][nt][2]; v.y = acc[mt][nt][3];
                    *(float2*)(r1p + nt * 8) = v;
                }
            }
        }
    }
}

// ---------------------------------------------------------------------------
extern "C" void kernel_launch(void* const* d_in, const int* in_sizes, int n_in,
                              void* d_out, int out_size) {
    const float* x       = (const float*)d_in[0];
    const float* weights = (const float*)d_in[1];
    const int*   scatter = (const int*)d_in[2];
    const int*   splits  = (const int*)d_in[3];
    float*       out     = (float*)d_out;
    (void)in_sizes; (void)n_in; (void)out_size;

    cudaFuncSetAttribute(moe_gemm_mma,
                         cudaFuncAttributeMaxDynamicSharedMemorySize, SMEM_TOTAL);

    build_token_map<<<MTOT / 256, 256>>>(scatter);
    build_tiles<<<1, 32>>>(splits);
    split_A<<<(NTOK * KDIM / 4) / 256, 256>>>(x);
    split_W<<<(NEXP * NDIM * KDIM / 4) / 256, 256>>>(weights);

    moe_gemm_mma<<<152, 256, SMEM_TOTAL>>>(out);   // persistent, 1 CTA/SM
}

// round 5
// speedup vs baseline: 1.2555x; 1.2555x over previous
#include <cuda_runtime.h>
#include <cuda_bf16.h>
#include <cstdint>

// ===========================================================================
// MoE AG-scatter grouped GEMM via mma.sync bf16, 2-term fp32 split (3 products)
//   out[s,:] = x[token(s),:] @ W[e(s),:,:]^T
// R5: R3's proven GEMM shape (CTA 128x128, 8 warps 4Mx2N, 2 CTA/SM, 2-stage
//     cp.async, 80B-stride smem) + persistent job loop (kills wave tail)
//     + fused one-kernel prep + per-token A split gathered via smem token list.
// ===========================================================================

#define NTOK   8192
#define TOPK   2
#define MTOT   (NTOK * TOPK)          // 16384
#define NDIM   1024
#define KDIM   1024
#define NEXP   8

#define BM     128
#define BN     128
#define BK     32                     // bf16 k per chunk
#define NCHUNK (KDIM / BK)            // 32
#define NBLK   (NDIM / BN)            // 8
#define MAXTILES (MTOT / BM + NEXP)   // 136

#define ASTR   80                     // smem row stride (64B data + 16B pad)
#define OFF_AH 0
#define OFF_AL (128 * ASTR)
#define OFF_BH (2 * 128 * ASTR)
#define OFF_BL (3 * 128 * ASTR)
#define STAGE_BYTES (4 * 128 * ASTR)  // 40960
#define SMEM_TOTAL  (2 * STAGE_BYTES + 512 + 16)

// ---------------- device-global scratch ------------------------------------
__device__ int g_token_of_row[MTOT];
__device__ int g_tile_e[MAXTILES];
__device__ int g_tile_row0[MAXTILES];
__device__ int g_tile_rows[MAXTILES];
__device__ int g_njobs;
__device__ int g_job;
__device__ __align__(16) __nv_bfloat16 g_A_hi[(size_t)NTOK * KDIM];
__device__ __align__(16) __nv_bfloat16 g_A_lo[(size_t)NTOK * KDIM];
__device__ __align__(16) __nv_bfloat16 g_W_hi[(size_t)NEXP * NDIM * KDIM];
__device__ __align__(16) __nv_bfloat16 g_W_lo[(size_t)NEXP * NDIM * KDIM];

// ---------------- helpers ---------------------------------------------------
__device__ __forceinline__ uint32_t smem_to_u32(const void* p) {
    uint32_t a;
    asm("{ .reg .u64 t; cvta.to.shared.u64 t, %1; cvt.u32.u64 %0, t; }"
        : "=r"(a) : "l"(p));
    return a;
}

#define CPA16(dst_u32, src_ptr) \
    asm volatile("cp.async.cg.shared.global [%0], [%1], 16;" \
        :: "r"(dst_u32), "l"(src_ptr))
#define CPA_COMMIT() asm volatile("cp.async.commit_group;")
#define CPA_WAIT1()  asm volatile("cp.async.wait_group 1;")
#define CPA_WAIT0()  asm volatile("cp.async.wait_group 0;")

__device__ __forceinline__ void ldsm_x4(uint32_t r[4], uint32_t addr) {
    asm volatile("ldmatrix.sync.aligned.m8n8.x4.shared.b16 {%0,%1,%2,%3}, [%4];"
        : "=r"(r[0]), "=r"(r[1]), "=r"(r[2]), "=r"(r[3]) : "r"(addr));
}

__device__ __forceinline__ void mma_bf16(float d[4],
    const uint32_t a[4], uint32_t b0, uint32_t b1)
{
    asm volatile(
        "mma.sync.aligned.m16n8k16.row.col.f32.bf16.bf16.f32 "
        "{%0,%1,%2,%3}, {%4,%5,%6,%7}, {%8,%9}, {%0,%1,%2,%3};"
        : "+f"(d[0]), "+f"(d[1]), "+f"(d[2]), "+f"(d[3])
        : "r"(a[0]), "r"(a[1]), "r"(a[2]), "r"(a[3]), "r"(b0), "r"(b1));
}

__device__ __forceinline__ void split_store(float4 v, __nv_bfloat16* hi,
                                            __nv_bfloat16* lo, size_t o)
{
    __nv_bfloat16 h0 = __float2bfloat16(v.x), h1 = __float2bfloat16(v.y);
    __nv_bfloat16 h2 = __float2bfloat16(v.z), h3 = __float2bfloat16(v.w);
    __nv_bfloat16 l0 = __float2bfloat16(v.x - __bfloat162float(h0));
    __nv_bfloat16 l1 = __float2bfloat16(v.y - __bfloat162float(h1));
    __nv_bfloat16 l2 = __float2bfloat16(v.z - __bfloat162float(h2));
    __nv_bfloat16 l3 = __float2bfloat16(v.w - __bfloat162float(h3));
    *(ushort4*)(hi + o) = make_ushort4(
        __bfloat16_as_ushort(h0), __bfloat16_as_ushort(h1),
        __bfloat16_as_ushort(h2), __bfloat16_as_ushort(h3));
    *(ushort4*)(lo + o) = make_ushort4(
        __bfloat16_as_ushort(l0), __bfloat16_as_ushort(l1),
        __bfloat16_as_ushort(l2), __bfloat16_as_ushort(l3));
}

// ---------------- fused prep -------------------------------------------------
// Blocks [0, 8192)            : split W
// Blocks [8192, 16384)        : split A (per token)
// Blocks [16384, 16448)       : token map
// Block  16448                : tile table
#define WBLK 8192
#define ABLK 8192
#define MBLK (MTOT / 256)             // 64
#define PREP_GRID (WBLK + ABLK + MBLK + 1)

__global__ __launch_bounds__(256) void prep_all(
    const float* __restrict__ x, const float* __restrict__ w,
    const int* __restrict__ scatter, const int* __restrict__ splits)
{
    int b = blockIdx.x;
    if (b < WBLK) {
        size_t o = ((size_t)b * 256 + threadIdx.x) * 4;
        split_store(*(const float4*)(w + o), g_W_hi, g_W_lo, o);
    } else if (b < WBLK + ABLK) {
        size_t o = ((size_t)(b - WBLK) * 256 + threadIdx.x) * 4;
        split_store(*(const float4*)(x + o), g_A_hi, g_A_lo, o);
    } else if (b < WBLK + ABLK + MBLK) {
        int f = (b - WBLK - ABLK) * 256 + threadIdx.x;
        g_token_of_row[scatter[f]] = f / TOPK;
    } else if (threadIdx.x == 0) {
        int cum = 0, t = 0;
        for (int e = 0; e < NEXP; e++) {
            int cnt = splits[e];
            for (int r0 = 0; r0 < cnt; r0 += BM) {
                g_tile_e[t] = e;
                g_tile_row0[t] = cum + r0;
                g_tile_rows[t] = (cnt - r0 < BM) ? (cnt - r0) : BM;
                t++;
            }
            cum += cnt;
        }
        g_njobs = t * NBLK;
        g_job = 0;
    }
}

// ---------------- main GEMM --------------------------------------------------
// Stage: 4 tiles x 128 rows x 64B data (80B stride), 2048 x 16B cp.async.
__device__ __forceinline__ void load_stage(uint32_t sbuf, int c, int wbase,
                                           const int* s_tok, int tid)
{
    const size_t kb = (size_t)c * BK;
    #pragma unroll
    for (int i = 0; i < 8; i++) {
        int o   = tid + i * 256;          // 0..2047
        int t4  = o >> 9;                 // 0=Ah,1=Al,2=Bh,3=Bl
        int r   = (o >> 2) & 127;
        int seg = (o & 3) * 16;
        uint32_t dst = sbuf + t4 * (128 * ASTR) + r * ASTR + seg;
        const char* src;
        if (t4 < 2) {
            int tok = s_tok[r];
            const __nv_bfloat16* base = (t4 == 0) ? g_A_hi : g_A_lo;
            src = (const char*)(base + (size_t)tok * KDIM + kb) + seg;
        } else {
            const __nv_bfloat16* base = (t4 == 2) ? g_W_hi : g_W_lo;
            src = (const char*)(base + (size_t)(wbase + r) * KDIM + kb) + seg;
        }
        CPA16(dst, src);
    }
}

__global__ __launch_bounds__(256, 2) void moe_gemm_mma(float* __restrict__ out)
{
    extern __shared__ char smem_raw[];
    const uint32_t st0 = smem_to_u32(smem_raw);
    const uint32_t st1 = st0 + STAGE_BYTES;
    int* s_tok = (int*)(smem_raw + 2 * STAGE_BYTES);
    int* s_job = (int*)(smem_raw + 2 * STAGE_BYTES + 512);

    const int tid  = threadIdx.x;
    const int wid  = tid >> 5;
    const int lane = tid & 31;
    const int wm   = wid & 3;          // 4 warps along M (32 rows each)
    const int wn   = wid >> 2;         // 2 warps along N (64 cols each)

    const int a_r   = (lane & 7) + ((lane >> 3) & 1) * 8;
    const int a_c16 = lane >> 4;
    uint32_t offA[2];
    #pragma unroll
    for (int mt = 0; mt < 2; mt++)
        offA[mt] = (wm * 32 + mt * 16 + a_r) * ASTR + a_c16 * 16;
    const int b_r   = (lane & 7) + ((lane >> 4) & 1) * 8;
    const int b_k16 = (lane >> 3) & 1;
    uint32_t offB[4];
    #pragma unroll
    for (int np = 0; np < 4; np++)
        offB[np] = (wn * 64 + np * 16 + b_r) * ASTR + b_k16 * 16;

    const int njobs = g_njobs;

    while (true) {
        __syncthreads();                          // smem free from previous job
        if (tid == 0) *s_job = atomicAdd(&g_job, 1);
        __syncthreads();
        const int job = *s_job;
        if (job >= njobs) break;

        const int tile = job >> 3;                // NBLK = 8
        const int nb   = job & 7;
        const int nrows = g_tile_rows[tile];
        const int row0  = g_tile_row0[tile];
        const int e     = g_tile_e[tile];
        const int n0    = nb * BN;
        const int wbase = e * NDIM + n0;

        if (tid < 128)
            s_tok[tid] = (tid < nrows) ? g_token_of_row[row0 + tid] : 0;
        __syncthreads();

        float acc[2][8][4];
        #pragma unroll
        for (int mt = 0; mt < 2; mt++)
            #pragma unroll
            for (int nt = 0; nt < 8; nt++)
                #pragma unroll
                for (int q = 0; q < 4; q++)
                    acc[mt][nt][q] = 0.0f;

        load_stage(st0, 0, wbase, s_tok, tid);
        CPA_COMMIT();
        load_stage(st1, 1, wbase, s_tok, tid);
        CPA_COMMIT();

        for (int c = 0; c < NCHUNK; c++) {
            const uint32_t sbuf = (c & 1) ? st1 : st0;
            if (c < NCHUNK - 1) { CPA_WAIT1(); } else { CPA_WAIT0(); }
            __syncthreads();

            #pragma unroll
            for (int ks = 0; ks < 2; ks++) {
                const uint32_t ko = ks * 32;      // 16 bf16 = 32B
                uint32_t Ah[2][4], Al[2][4];
                #pragma unroll
                for (int mt = 0; mt < 2; mt++) {
                    ldsm_x4(Ah[mt], sbuf + OFF_AH + offA[mt] + ko);
                    ldsm_x4(Al[mt], sbuf + OFF_AL + offA[mt] + ko);
                }
                #pragma unroll
                for (int np = 0; np < 4; np++) {
                    uint32_t Bh[4], Bl[4];
                    ldsm_x4(Bh, sbuf + OFF_BH + offB[np] + ko);
                    ldsm_x4(Bl, sbuf + OFF_BL + offB[np] + ko);
                    #pragma unroll
                    for (int mt = 0; mt < 2; mt++) {
                        float* d0 = acc[mt][2 * np];
                        float* d1 = acc[mt][2 * np + 1];
                        mma_bf16(d0, Ah[mt], Bh[0], Bh[1]);
                        mma_bf16(d1, Ah[mt], Bh[2], Bh[3]);
                        mma_bf16(d0, Ah[mt], Bl[0], Bl[1]);
                        mma_bf16(d1, Ah[mt], Bl[2], Bl[3]);
                        mma_bf16(d0, Al[mt], Bh[0], Bh[1]);
                        mma_bf16(d1, Al[mt], Bh[2], Bh[3]);
                    }
                }
            }

            __syncthreads();
            if (c + 2 < NCHUNK) {
                load_stage(sbuf, c + 2, wbase, s_tok, tid);
                CPA_COMMIT();
            }
        }

        // epilogue
        const int g = lane >> 2;
        const int t = lane & 3;
        #pragma unroll
        for (int mt = 0; mt < 2; mt++) {
            const int mBase = wm * 32 + mt * 16;
            const int m0 = mBase + g;
            const int m1 = mBase + g + 8;
            float* r0p = out + (size_t)(row0 + m0) * NDIM + n0 + wn * 64 + 2 * t;
            float* r1p = out + (size_t)(row0 + m1) * NDIM + n0 + wn * 64 + 2 * t;
            #pragma unroll
            for (int nt = 0; nt < 8; nt++) {
                if (m0 < nrows) {
                    float2 v; v.x = acc[mt][nt][0]; v.y = acc[mt][nt][1];
                    *(float2*)(r0p + nt * 8) = v;
                }
                if (m1 < nrows) {
                    float2 v; v.x = acc[mt][nt][2]; v.y = acc[mt][nt][3];
                    *(float2*)(r1p + nt * 8) = v;
                }
            }
        }
    }
}

// ---------------------------------------------------------------------------
extern "C" void kernel_launch(void* const* d_in, const int* in_sizes, int n_in,
                              void* d_out, int out_size) {
    const float* x       = (const float*)d_in[0];
    const float* weights = (const float*)d_in[1];
    const int*   scatter = (const int*)d_in[2];
    const int*   splits  = (const int*)d_in[3];
    float*       out     = (float*)d_out;
    (void)in_sizes; (void)n_in; (void)out_size;

    cudaFuncSetAttribute(moe_gemm_mma,
                         cudaFuncAttributeMaxDynamicSharedMemorySize, SMEM_TOTAL);

    prep_all<<<PREP_GRID, 256>>>(x, weights, scatter, splits);
    moe_gemm_mma<<<304, 256, SMEM_TOTAL>>>(out);   // persistent, 2 CTAs/SM
}